// round 5
// baseline (speedup 1.0000x reference)
#include <cuda_runtime.h>
#include <cuda_bf16.h>
#include <cstdint>

#define CO   256
#define CI   2048
#define HW   1024
#define NB   8

__device__ unsigned int   g_amax;
__device__ __nv_bfloat16  g_wq[CO * CI];
__device__ float          g_scale[CO];
__device__ float          g_bq[CO];

__device__ __forceinline__ uint32_t smem_u32(const void* p) {
    return static_cast<uint32_t>(__cvta_generic_to_shared(p));
}

__global__ void init_kernel() { g_amax = 0u; }

__global__ void amax_kernel(const float* __restrict__ x, int n4) {
    const float4* x4 = reinterpret_cast<const float4*>(x);
    float m = 0.f;
    for (int i = blockIdx.x * blockDim.x + threadIdx.x; i < n4; i += gridDim.x * blockDim.x) {
        float4 v = x4[i];
        m = fmaxf(m, fmaxf(fmaxf(fabsf(v.x), fabsf(v.y)), fmaxf(fabsf(v.z), fabsf(v.w))));
    }
    #pragma unroll
    for (int o = 16; o; o >>= 1) m = fmaxf(m, __shfl_xor_sync(0xffffffffu, m, o));
    __shared__ float red[8];
    if ((threadIdx.x & 31) == 0) red[threadIdx.x >> 5] = m;
    __syncthreads();
    if (threadIdx.x < 8) {
        m = red[threadIdx.x];
        #pragma unroll
        for (int o = 4; o; o >>= 1) m = fmaxf(m, __shfl_xor_sync(0xffu, m, o));
        if (threadIdx.x == 0) atomicMax(&g_amax, __float_as_uint(m));
    }
}

__global__ void wprep_kernel(const float* __restrict__ w, const float* __restrict__ bias) {
    const int co  = blockIdx.x;
    const int tid = threadIdx.x;
    const float* wr = w + (size_t)co * CI;
    float vals[8];
    float m = 0.f;
    #pragma unroll
    for (int j = 0; j < 8; j++) {
        vals[j] = wr[tid + 256 * j];
        m = fmaxf(m, fabsf(vals[j]));
    }
    #pragma unroll
    for (int o = 16; o; o >>= 1) m = fmaxf(m, __shfl_xor_sync(0xffffffffu, m, o));
    __shared__ float red[8];
    __shared__ float s_sw_sh;
    if ((tid & 31) == 0) red[tid >> 5] = m;
    __syncthreads();
    if (tid == 0) {
        float mm = red[0];
        #pragma unroll
        for (int i = 1; i < 8; i++) mm = fmaxf(mm, red[i]);
        float s_w = fmaxf(mm, 1e-8f) / 127.f;
        s_sw_sh = s_w;
        float s_a = fmaxf(__uint_as_float(g_amax), 1e-8f) / 127.f;
        float s_b = s_a * s_w;
        g_scale[co] = s_b;
        g_bq[co]    = rintf(bias[co] / s_b) * s_b;
    }
    __syncthreads();
    const float s_w = s_sw_sh;
    #pragma unroll
    for (int j = 0; j < 8; j++) {
        float q = fminf(fmaxf(rintf(vals[j] / s_w), -128.f), 127.f);
        g_wq[(size_t)co * CI + tid + 256 * j] = __float2bfloat16(q);
    }
}

// ---------------- GEMM: BM=128, BN=64, BK=32, 3-stage pipeline ----------------
#define BM   128
#define BN   64
#define BK   32
#define NSTG 3
#define ASTR 40     // A smem row stride (bf16 elems) -> 80B, 16B aligned
#define BSTR 72     // B smem row stride (bf16 elems) -> 144B, 16B aligned
#define KT_N (CI / BK)   // 64

__global__ __launch_bounds__(256, 2) void gemm_kernel(const float* __restrict__ x,
                                                      float* __restrict__ out) {
    __shared__ __align__(16) __nv_bfloat16 As[NSTG][BM * ASTR];
    __shared__ __align__(16) __nv_bfloat16 Bs[NSTG][BK * BSTR];

    const int tid  = threadIdx.x;
    const int lane = tid & 31;
    const int warp = tid >> 5;
    const int wm   = warp >> 1;   // 0..3 -> 32 rows
    const int wn   = warp & 1;    // 0..1 -> 32 cols

    const int tileM = blockIdx.x;            // 0..1 (fastest -> L2 x reuse)
    const int tileN = blockIdx.y;            // 0..127
    const int b     = tileN >> 4;
    const int hw0   = (tileN & 15) * BN;
    const float* xb = x + (size_t)b * CI * HW + hw0;

    const float s_a    = fmaxf(__uint_as_float(g_amax), 1e-8f) / 127.f;
    const float inv_sa = 1.f / s_a;
    const float MAGIC  = 12582912.f;   // 1.5 * 2^23

    // B (x) loader: 32 k-rows x 64 n-cols fp32; 2 float4 per thread
    const int brow = tid >> 4;          // 0..15, +16
    const int bcol = (tid & 15) * 4;    // 0..60
    // A (wq) loader via cp.async: 128 rows x 32 cols bf16; 2x16B per thread
    const int arow = tid >> 2;          // 0..63, +64
    const int acol = (tid & 3) * 8;     // 0,8,16,24

    const __nv_bfloat16* wq = g_wq + (size_t)(tileM * BM) * CI;

    float4 bReg[2][2];   // [parity][row chunk]

    auto loadB = [&](int kt) {
        const float* xp = xb + (size_t)(kt * BK) * HW;
        bReg[kt & 1][0] = *reinterpret_cast<const float4*>(xp + (size_t)brow * HW + bcol);
        bReg[kt & 1][1] = *reinterpret_cast<const float4*>(xp + (size_t)(brow + 16) * HW + bcol);
    };
    auto storeB = [&](int kt) {
        const int st = kt % NSTG;
        const int pa = kt & 1;
        #pragma unroll
        for (int i = 0; i < 2; i++) {
            float4 v = bReg[pa][i];
            float q0 = fmaf(v.x, inv_sa, MAGIC) - MAGIC;
            float q1 = fmaf(v.y, inv_sa, MAGIC) - MAGIC;
            float q2 = fmaf(v.z, inv_sa, MAGIC) - MAGIC;
            float q3 = fmaf(v.w, inv_sa, MAGIC) - MAGIC;
            __nv_bfloat162* dst =
                reinterpret_cast<__nv_bfloat162*>(&Bs[st][(brow + 16 * i) * BSTR + bcol]);
            dst[0] = __floats2bfloat162_rn(q0, q1);
            dst[1] = __floats2bfloat162_rn(q2, q3);
        }
    };
    auto loadA = [&](int kt) {
        const int st = kt % NSTG;
        const __nv_bfloat16* wp = wq + kt * BK;
        #pragma unroll
        for (int i = 0; i < 2; i++) {
            uint32_t dst = smem_u32(&As[st][(arow + 64 * i) * ASTR + acol]);
            const void* src = wp + (size_t)(arow + 64 * i) * CI + acol;
            asm volatile("cp.async.cg.shared.global [%0], [%1], 16;\n" :: "r"(dst), "l"(src));
        }
        asm volatile("cp.async.commit_group;\n");
    };

    // ---- prologue: stages 0,1 in smem; x for stage 2 in regs ----
    loadB(0);
    loadB(1);
    loadA(0);
    loadA(1);
    storeB(0);
    storeB(1);
    loadB(2);
    asm volatile("cp.async.wait_group 1;\n");   // A0 ready
    __syncthreads();

    float acc[2][4][4];
    #pragma unroll
    for (int mt = 0; mt < 2; mt++)
        #pragma unroll
        for (int nt = 0; nt < 4; nt++)
            #pragma unroll
            for (int r = 0; r < 4; r++) acc[mt][nt][r] = 0.f;

    for (int kt = 0; kt < KT_N; kt++) {
        const int cur = kt % NSTG;
        const int pf  = kt + 2;
        // memory issue first: fill stage kt+2, prefetch x for kt+3
        if (pf < KT_N) {
            storeB(pf);
            loadA(pf);
        }
        if (kt + 3 < KT_N) loadB(kt + 3);

        // compute on stage cur
        #pragma unroll
        for (int kk = 0; kk < 2; kk++) {
            uint32_t a[2][4];
            #pragma unroll
            for (int mt = 0; mt < 2; mt++) {
                int mr = wm * 32 + mt * 16 + (lane & 15);
                int kc = kk * 16 + (lane >> 4) * 8;
                uint32_t addr = smem_u32(&As[cur][mr * ASTR + kc]);
                asm volatile("ldmatrix.sync.aligned.m8n8.x4.shared.b16 {%0,%1,%2,%3}, [%4];"
                             : "=r"(a[mt][0]), "=r"(a[mt][1]), "=r"(a[mt][2]), "=r"(a[mt][3])
                             : "r"(addr));
            }
            uint32_t bf[2][4];
            #pragma unroll
            for (int np = 0; np < 2; np++) {
                int kr = kk * 16 + (lane & 15);
                int nc = wn * 32 + np * 16 + (lane >> 4) * 8;
                uint32_t addr = smem_u32(&Bs[cur][kr * BSTR + nc]);
                asm volatile("ldmatrix.sync.aligned.m8n8.x4.trans.shared.b16 {%0,%1,%2,%3}, [%4];"
                             : "=r"(bf[np][0]), "=r"(bf[np][1]), "=r"(bf[np][2]), "=r"(bf[np][3])
                             : "r"(addr));
            }
            #pragma unroll
            for (int mt = 0; mt < 2; mt++) {
                #pragma unroll
                for (int nt = 0; nt < 4; nt++) {
                    uint32_t b0 = bf[nt >> 1][(nt & 1) * 2 + 0];
                    uint32_t b1 = bf[nt >> 1][(nt & 1) * 2 + 1];
                    asm volatile(
                        "mma.sync.aligned.m16n8k16.row.col.f32.bf16.bf16.f32 "
                        "{%0,%1,%2,%3}, {%4,%5,%6,%7}, {%8,%9}, {%0,%1,%2,%3};"
                        : "+f"(acc[mt][nt][0]), "+f"(acc[mt][nt][1]),
                          "+f"(acc[mt][nt][2]), "+f"(acc[mt][nt][3])
                        : "r"(a[mt][0]), "r"(a[mt][1]), "r"(a[mt][2]), "r"(a[mt][3]),
                          "r"(b0), "r"(b1));
                }
            }
        }

        // ensure A(kt+1) landed, then release/rotate buffers
        if (pf < KT_N) {
            asm volatile("cp.async.wait_group 1;\n");
        } else {
            asm volatile("cp.async.wait_group 0;\n");
        }
        __syncthreads();
    }

    // epilogue
    #pragma unroll
    for (int mt = 0; mt < 2; mt++) {
        int co0 = tileM * BM + wm * 32 + mt * 16 + (lane >> 2);
        float s0 = g_scale[co0],     q0 = g_bq[co0];
        float s1 = g_scale[co0 + 8], q1 = g_bq[co0 + 8];
        #pragma unroll
        for (int nt = 0; nt < 4; nt++) {
            int hw = hw0 + wn * 32 + nt * 8 + (lane & 3) * 2;
            float* o = out + (size_t)b * CO * HW + (size_t)co0 * HW + hw;
            float2 v0 = make_float2(acc[mt][nt][0] * s0 + q0, acc[mt][nt][1] * s0 + q0);
            float2 v1 = make_float2(acc[mt][nt][2] * s1 + q1, acc[mt][nt][3] * s1 + q1);
            *reinterpret_cast<float2*>(o) = v0;
            *reinterpret_cast<float2*>(o + 8 * HW) = v1;
        }
    }
}

extern "C" void kernel_launch(void* const* d_in, const int* in_sizes, int n_in,
                              void* d_out, int out_size) {
    const float* x    = (const float*)d_in[0];
    const float* w    = (const float*)d_in[1];
    const float* bias = (const float*)d_in[2];
    float* out        = (float*)d_out;

    init_kernel<<<1, 1>>>();
    const int n4 = (NB * CI * HW) / 4;
    amax_kernel<<<1024, 256>>>(x, n4);
    wprep_kernel<<<CO, 256>>>(w, bias);
    dim3 grid(2, 128);
    gemm_kernel<<<grid, 256>>>(x, out);
}

// round 6
// speedup vs baseline: 1.1611x; 1.1611x over previous
#include <cuda_runtime.h>
#include <cuda_bf16.h>
#include <cstdint>

#define CO   256
#define CI   2048
#define HW   1024
#define NB   8

__device__ unsigned int   g_amax;
__device__ __nv_bfloat16  g_wq[CO * CI];
__device__ float          g_scale[CO];
__device__ float          g_bq[CO];

__device__ __forceinline__ uint32_t smem_u32(const void* p) {
    return static_cast<uint32_t>(__cvta_generic_to_shared(p));
}

__global__ void init_kernel() { g_amax = 0u; }

__global__ void amax_kernel(const float* __restrict__ x, int n4) {
    const float4* x4 = reinterpret_cast<const float4*>(x);
    float m = 0.f;
    for (int i = blockIdx.x * blockDim.x + threadIdx.x; i < n4; i += gridDim.x * blockDim.x) {
        float4 v = x4[i];
        m = fmaxf(m, fmaxf(fmaxf(fabsf(v.x), fabsf(v.y)), fmaxf(fabsf(v.z), fabsf(v.w))));
    }
    #pragma unroll
    for (int o = 16; o; o >>= 1) m = fmaxf(m, __shfl_xor_sync(0xffffffffu, m, o));
    __shared__ float red[8];
    if ((threadIdx.x & 31) == 0) red[threadIdx.x >> 5] = m;
    __syncthreads();
    if (threadIdx.x < 8) {
        m = red[threadIdx.x];
        #pragma unroll
        for (int o = 4; o; o >>= 1) m = fmaxf(m, __shfl_xor_sync(0xffu, m, o));
        if (threadIdx.x == 0) atomicMax(&g_amax, __float_as_uint(m));
    }
}

__global__ void wprep_kernel(const float* __restrict__ w, const float* __restrict__ bias) {
    const int co  = blockIdx.x;
    const int tid = threadIdx.x;
    const float* wr = w + (size_t)co * CI;
    float vals[8];
    float m = 0.f;
    #pragma unroll
    for (int j = 0; j < 8; j++) {
        vals[j] = wr[tid + 256 * j];
        m = fmaxf(m, fabsf(vals[j]));
    }
    #pragma unroll
    for (int o = 16; o; o >>= 1) m = fmaxf(m, __shfl_xor_sync(0xffffffffu, m, o));
    __shared__ float red[8];
    __shared__ float s_sw_sh;
    if ((tid & 31) == 0) red[tid >> 5] = m;
    __syncthreads();
    if (tid == 0) {
        float mm = red[0];
        #pragma unroll
        for (int i = 1; i < 8; i++) mm = fmaxf(mm, red[i]);
        float s_w = fmaxf(mm, 1e-8f) / 127.f;
        s_sw_sh = s_w;
        float s_a = fmaxf(__uint_as_float(g_amax), 1e-8f) / 127.f;
        float s_b = s_a * s_w;
        g_scale[co] = s_b;
        g_bq[co]    = rintf(bias[co] / s_b) * s_b;
    }
    __syncthreads();
    const float s_w = s_sw_sh;
    #pragma unroll
    for (int j = 0; j < 8; j++) {
        float q = fminf(fmaxf(rintf(vals[j] / s_w), -128.f), 127.f);
        g_wq[(size_t)co * CI + tid + 256 * j] = __float2bfloat16(q);
    }
}

// ---------------- GEMM: BM=128, BN=64, BK=64, double-buffered ----------------
#define BM   128
#define BN   64
#define BK   64
#define ASTR 72     // A smem row stride (bf16) -> 144B
#define BSTR 72     // B smem row stride (bf16) -> 144B
#define KT_N (CI / BK)   // 32

#define A_STAGE (BM * ASTR)          // elems
#define B_STAGE (BK * BSTR)
#define SMEM_ELEMS (2 * (A_STAGE + B_STAGE))
#define SMEM_BYTES (SMEM_ELEMS * 2)

__global__ __launch_bounds__(256, 2) void gemm_kernel(const float* __restrict__ x,
                                                      float* __restrict__ out) {
    extern __shared__ __align__(16) __nv_bfloat16 sm[];
    __nv_bfloat16* As[2] = { sm, sm + A_STAGE };
    __nv_bfloat16* Bs[2] = { sm + 2 * A_STAGE, sm + 2 * A_STAGE + B_STAGE };

    const int tid  = threadIdx.x;
    const int lane = tid & 31;
    const int warp = tid >> 5;
    const int wm   = warp >> 1;   // 0..3 -> 32 rows
    const int wn   = warp & 1;    // 0..1 -> 32 cols

    const int tileM = blockIdx.x;            // 0..1 (fastest -> L2 x reuse)
    const int tileN = blockIdx.y;            // 0..127
    const int b     = tileN >> 4;
    const int hw0   = (tileN & 15) * BN;
    const float* xb = x + (size_t)b * CI * HW + hw0;

    const float s_a    = fmaxf(__uint_as_float(g_amax), 1e-8f) / 127.f;
    const float inv_sa = 1.f / s_a;
    const float MAGIC  = 12582912.f;   // 1.5 * 2^23

    // B (x) loader: 64 k-rows x 64 n-cols fp32; 4 float4 per thread
    const int brow = tid >> 4;          // 0..15, +16*i (i=0..3)
    const int bcol = (tid & 15) * 4;    // 0..60
    // A (wq) loader via cp.async: 128 rows x 64 cols bf16; 4x16B per thread
    const int arow = tid >> 1;          // 0..127
    const int acol = (tid & 1) * 32;    // 0 or 32 (then +8*j)

    const __nv_bfloat16* wq = g_wq + (size_t)(tileM * BM) * CI;

    float4 bReg[4];

    auto loadB = [&](int kt) {
        const float* xp = xb + (size_t)(kt * BK) * HW;
        #pragma unroll
        for (int i = 0; i < 4; i++)
            bReg[i] = *reinterpret_cast<const float4*>(xp + (size_t)(brow + 16 * i) * HW + bcol);
    };
    auto storeB = [&](int st) {
        #pragma unroll
        for (int i = 0; i < 4; i++) {
            float4 v = bReg[i];
            float q0 = fmaf(v.x, inv_sa, MAGIC) - MAGIC;
            float q1 = fmaf(v.y, inv_sa, MAGIC) - MAGIC;
            float q2 = fmaf(v.z, inv_sa, MAGIC) - MAGIC;
            float q3 = fmaf(v.w, inv_sa, MAGIC) - MAGIC;
            __nv_bfloat162* dst =
                reinterpret_cast<__nv_bfloat162*>(&Bs[st][(brow + 16 * i) * BSTR + bcol]);
            dst[0] = __floats2bfloat162_rn(q0, q1);
            dst[1] = __floats2bfloat162_rn(q2, q3);
        }
    };
    auto loadA = [&](int kt, int st) {
        const __nv_bfloat16* wp = wq + kt * BK + (size_t)arow * CI + acol;
        uint32_t dst = smem_u32(&As[st][arow * ASTR + acol]);
        #pragma unroll
        for (int j = 0; j < 4; j++) {
            asm volatile("cp.async.cg.shared.global [%0], [%1], 16;\n"
                         :: "r"(dst + j * 16), "l"(wp + j * 8));
        }
        asm volatile("cp.async.commit_group;\n");
    };

    // prologue: stage 0
    loadA(0, 0);
    loadB(0);
    storeB(0);
    asm volatile("cp.async.wait_group 0;\n");
    __syncthreads();

    float acc[2][4][4];
    #pragma unroll
    for (int mt = 0; mt < 2; mt++)
        #pragma unroll
        for (int nt = 0; nt < 4; nt++)
            #pragma unroll
            for (int r = 0; r < 4; r++) acc[mt][nt][r] = 0.f;

    for (int kt = 0; kt < KT_N; kt++) {
        const int cur = kt & 1;
        const int nxt = cur ^ 1;
        if (kt + 1 < KT_N) {
            loadA(kt + 1, nxt);
            loadB(kt + 1);
        }

        #pragma unroll
        for (int kk = 0; kk < 4; kk++) {
            uint32_t a[2][4];
            #pragma unroll
            for (int mt = 0; mt < 2; mt++) {
                int mr = wm * 32 + mt * 16 + (lane & 15);
                int kc = kk * 16 + (lane >> 4) * 8;
                uint32_t addr = smem_u32(&As[cur][mr * ASTR + kc]);
                asm volatile("ldmatrix.sync.aligned.m8n8.x4.shared.b16 {%0,%1,%2,%3}, [%4];"
                             : "=r"(a[mt][0]), "=r"(a[mt][1]), "=r"(a[mt][2]), "=r"(a[mt][3])
                             : "r"(addr));
            }
            uint32_t bf[2][4];
            #pragma unroll
            for (int np = 0; np < 2; np++) {
                int kr = kk * 16 + (lane & 15);
                int nc = wn * 32 + np * 16 + (lane >> 4) * 8;
                uint32_t addr = smem_u32(&Bs[cur][kr * BSTR + nc]);
                asm volatile("ldmatrix.sync.aligned.m8n8.x4.trans.shared.b16 {%0,%1,%2,%3}, [%4];"
                             : "=r"(bf[np][0]), "=r"(bf[np][1]), "=r"(bf[np][2]), "=r"(bf[np][3])
                             : "r"(addr));
            }
            #pragma unroll
            for (int mt = 0; mt < 2; mt++) {
                #pragma unroll
                for (int nt = 0; nt < 4; nt++) {
                    uint32_t b0 = bf[nt >> 1][(nt & 1) * 2 + 0];
                    uint32_t b1 = bf[nt >> 1][(nt & 1) * 2 + 1];
                    asm volatile(
                        "mma.sync.aligned.m16n8k16.row.col.f32.bf16.bf16.f32 "
                        "{%0,%1,%2,%3}, {%4,%5,%6,%7}, {%8,%9}, {%0,%1,%2,%3};"
                        : "+f"(acc[mt][nt][0]), "+f"(acc[mt][nt][1]),
                          "+f"(acc[mt][nt][2]), "+f"(acc[mt][nt][3])
                        : "r"(a[mt][0]), "r"(a[mt][1]), "r"(a[mt][2]), "r"(a[mt][3]),
                          "r"(b0), "r"(b1));
                }
            }
        }

        if (kt + 1 < KT_N) {
            storeB(nxt);
            asm volatile("cp.async.wait_group 0;\n");
        }
        __syncthreads();
    }

    // epilogue
    #pragma unroll
    for (int mt = 0; mt < 2; mt++) {
        int co0 = tileM * BM + wm * 32 + mt * 16 + (lane >> 2);
        float s0 = g_scale[co0],     q0 = g_bq[co0];
        float s1 = g_scale[co0 + 8], q1 = g_bq[co0 + 8];
        #pragma unroll
        for (int nt = 0; nt < 4; nt++) {
            int hw = hw0 + wn * 32 + nt * 8 + (lane & 3) * 2;
            float* o = out + (size_t)b * CO * HW + (size_t)co0 * HW + hw;
            float2 v0 = make_float2(acc[mt][nt][0] * s0 + q0, acc[mt][nt][1] * s0 + q0);
            float2 v1 = make_float2(acc[mt][nt][2] * s1 + q1, acc[mt][nt][3] * s1 + q1);
            *reinterpret_cast<float2*>(o) = v0;
            *reinterpret_cast<float2*>(o + 8 * HW) = v1;
        }
    }
}

extern "C" void kernel_launch(void* const* d_in, const int* in_sizes, int n_in,
                              void* d_out, int out_size) {
    const float* x    = (const float*)d_in[0];
    const float* w    = (const float*)d_in[1];
    const float* bias = (const float*)d_in[2];
    float* out        = (float*)d_out;

    cudaFuncSetAttribute(gemm_kernel, cudaFuncAttributeMaxDynamicSharedMemorySize, SMEM_BYTES);

    init_kernel<<<1, 1>>>();
    const int n4 = (NB * CI * HW) / 4;
    amax_kernel<<<1024, 256>>>(x, n4);
    wprep_kernel<<<CO, 256>>>(w, bias);
    dim3 grid(2, 128);
    gemm_kernel<<<grid, 256, SMEM_BYTES>>>(x, out);
}